// round 7
// baseline (speedup 1.0000x reference)
#include <cuda_runtime.h>
#include <cstdint>

// VQBlock via mma.sync tf32x3 + exact-fp32 rescue for near-tie rows.
// x [65536, 256] fp32, dict [256, 1024] fp32.
// out[0..N*D) = q_st, out[N*D] = 1.25 * mean((x-q)^2)

#define D_DIM 256
#define K_CODES 1024
#define N_ROWS 65536
#define M_TILE 128
#define N_TILE 128
#define KD 32
#define NSTAGES 64                    // 8 code-chunks x 8 depth-stages
#define PAD 44                        // floats per smem tile row (16B-mult, bank-free)
#define MAT_FLOATS (128 * PAD)
#define MAT_BYTES  (MAT_FLOATS * 4)   // 22528
#define BUF_BYTES  (4 * MAT_BYTES)    // Ahi|Alo|Bhi|Blo = 90112
#define OFF_CNORM  (2 * BUF_BYTES)    // 4096 B
#define OFF_SB     (OFF_CNORM + 4096) // 2048 B
#define OFF_SS     (OFF_SB + 2048)    // 2048 B
#define OFF_SK     (OFF_SS + 2048)    // 2048 B
#define SMEM_TOTAL (OFF_SK + 2048)
#define GAP_THRESH 2e-3f

__device__ float  g_cnorm[K_CODES];
__device__ float  g_rnorm[N_ROWS];
__device__ float  g_dictT[K_CODES * D_DIM];   // fp32 [code][d]
__device__ float  g_dThi[K_CODES * D_DIM];    // tf32 hi [code][d]
__device__ float  g_dTlo[K_CODES * D_DIM];    // tf32 lo
__device__ float  g_xhi[N_ROWS * D_DIM];
__device__ float  g_xlo[N_ROWS * D_DIM];
__device__ int    g_rowk[N_ROWS];
__device__ int    g_flagrows[N_ROWS];
__device__ int    g_nflag;
__device__ double g_sum;

// ---------------------------------------------------------------------------
__device__ __forceinline__ uint32_t smem_u32(const void* p) {
    uint32_t a;
    asm("{ .reg .u64 t; cvta.to.shared.u64 t, %1; cvt.u32.u64 %0, t; }"
        : "=r"(a) : "l"(p));
    return a;
}
__device__ __forceinline__ float tf32_hi(float v) {
    uint32_t r;
    asm("cvt.rna.tf32.f32 %0, %1;" : "=r"(r) : "f"(v));
    return __uint_as_float(r);
}
__device__ __forceinline__ void cp16(uint32_t dst, const void* src) {
    asm volatile("cp.async.cg.shared.global [%0], [%1], 16;"
                 :: "r"(dst), "l"(src) : "memory");
}
__device__ __forceinline__ void mma8(float* c, const uint32_t* a, const uint32_t* b) {
    asm volatile(
        "mma.sync.aligned.m16n8k8.row.col.f32.tf32.tf32.f32 "
        "{%0,%1,%2,%3}, {%4,%5,%6,%7}, {%8,%9}, {%0,%1,%2,%3};"
        : "+f"(c[0]), "+f"(c[1]), "+f"(c[2]), "+f"(c[3])
        : "r"(a[0]), "r"(a[1]), "r"(a[2]), "r"(a[3]), "r"(b[0]), "r"(b[1]));
}

// ---------------------------------------------------------------------------
__global__ void split_dict_kernel(const float* __restrict__ dict) {
    int gt = blockIdx.x * blockDim.x + threadIdx.x;
    if (gt == 0) { g_sum = 0.0; g_nflag = 0; }
    int warp = gt >> 5;
    int lane = threadIdx.x & 31;
    if (warp >= K_CODES) return;
    double s = 0.0;
    for (int d = lane; d < D_DIM; d += 32) {
        float v = dict[d * K_CODES + warp];
        s += (double)v * v;
        float h = tf32_hi(v);
        float l = tf32_hi(v - h);
        size_t o = (size_t)warp * D_DIM + d;
        g_dictT[o] = v;
        g_dThi[o] = h;
        g_dTlo[o] = l;
    }
#pragma unroll
    for (int o = 16; o > 0; o >>= 1) s += __shfl_xor_sync(0xffffffff, s, o);
    if (lane == 0) g_cnorm[warp] = (float)s;
}

__global__ void split_x_kernel(const float* __restrict__ x) {
    int warp = (blockIdx.x * blockDim.x + threadIdx.x) >> 5;
    int lane = threadIdx.x & 31;
    if (warp >= N_ROWS) return;
    const float4* p = (const float4*)(x + (size_t)warp * D_DIM);
    float4 a = p[lane];
    float4 b = p[lane + 32];
    double s = (double)a.x * a.x + (double)a.y * a.y
             + (double)a.z * a.z + (double)a.w * a.w
             + (double)b.x * b.x + (double)b.y * b.y
             + (double)b.z * b.z + (double)b.w * b.w;
    float4 ah, al, bh, bl;
    ah.x = tf32_hi(a.x); al.x = tf32_hi(a.x - ah.x);
    ah.y = tf32_hi(a.y); al.y = tf32_hi(a.y - ah.y);
    ah.z = tf32_hi(a.z); al.z = tf32_hi(a.z - ah.z);
    ah.w = tf32_hi(a.w); al.w = tf32_hi(a.w - ah.w);
    bh.x = tf32_hi(b.x); bl.x = tf32_hi(b.x - bh.x);
    bh.y = tf32_hi(b.y); bl.y = tf32_hi(b.y - bh.y);
    bh.z = tf32_hi(b.z); bl.z = tf32_hi(b.z - bh.z);
    bh.w = tf32_hi(b.w); bl.w = tf32_hi(b.w - bh.w);
    float4* ph = (float4*)(g_xhi + (size_t)warp * D_DIM);
    float4* pl = (float4*)(g_xlo + (size_t)warp * D_DIM);
    ph[lane] = ah; ph[lane + 32] = bh;
    pl[lane] = al; pl[lane + 32] = bl;
#pragma unroll
    for (int o = 16; o > 0; o >>= 1) s += __shfl_xor_sync(0xffffffff, s, o);
    if (lane == 0) g_rnorm[warp] = (float)s;
}

// ---------------------------------------------------------------------------
// Main GEMM+argmin: 512 threads (16 warps as 4x4), one 128-row tile per block.
__global__ __launch_bounds__(512, 1) void vq_tc() {
    extern __shared__ char smem[];
    const uint32_t smu = smem_u32(smem);
    const int tid = threadIdx.x;
    const int lane = tid & 31;
    const int wid = tid >> 5;
    const int wm = wid >> 2;
    const int wn = wid & 3;
    const int gid = lane >> 2;
    const int tig = lane & 3;
    const int row0 = blockIdx.x * M_TILE;

    float* s_cn = (float*)(smem + OFF_CNORM);
    for (int i = tid; i < K_CODES; i += 512) s_cn[i] = g_cnorm[i];

    float rn[4], best[4], sec[4];
    int bestk[4];
#pragma unroll
    for (int bi = 0; bi < 4; bi++) {
        int row = wm * 32 + (bi >> 1) * 16 + (bi & 1) * 8 + gid;
        rn[bi] = g_rnorm[row0 + row];
        best[bi] = 3.4e38f;
        sec[bi] = 3.4e38f;
        bestk[bi] = 0;
    }

    auto issue = [&](int g) {
        int nt = g >> 3, c = g & 7;
        uint32_t buf = smu + (uint32_t)(g & 1) * BUF_BYTES;
        int kb = c * KD;
#pragma unroll
        for (int h = 0; h < 2; h++) {
            int q = tid + h * 512;
            int row = q >> 3, c4 = q & 7;
            uint32_t dst = buf + (uint32_t)(row * (PAD * 4) + c4 * 16);
            size_t sa = (size_t)(row0 + row) * D_DIM + kb + c4 * 4;
            size_t sbg = (size_t)(nt * N_TILE + row) * D_DIM + kb + c4 * 4;
            cp16(dst, g_xhi + sa);
            cp16(dst + MAT_BYTES, g_xlo + sa);
            cp16(dst + 2 * MAT_BYTES, g_dThi + sbg);
            cp16(dst + 3 * MAT_BYTES, g_dTlo + sbg);
        }
        asm volatile("cp.async.commit_group;" ::: "memory");
    };

    float acc[2][4][4];
    issue(0);

    for (int g = 0; g < NSTAGES; g++) {
        const int nt = g >> 3, c = g & 7;
        if (g + 1 < NSTAGES) {
            issue(g + 1);
            asm volatile("cp.async.wait_group 1;" ::: "memory");
        } else {
            asm volatile("cp.async.wait_group 0;" ::: "memory");
        }
        __syncthreads();

        if (c == 0) {
#pragma unroll
            for (int ma = 0; ma < 2; ma++)
#pragma unroll
                for (int na = 0; na < 4; na++)
#pragma unroll
                    for (int j = 0; j < 4; j++) acc[ma][na][j] = 0.f;
        }

        const float* sAhi = (const float*)(smem + (g & 1) * BUF_BYTES);
        const float* sAlo = sAhi + MAT_FLOATS;
        const float* sBhi = sAlo + MAT_FLOATS;
        const float* sBlo = sBhi + MAT_FLOATS;

#pragma unroll
        for (int ks = 0; ks < 4; ks++) {
            const int k0 = ks * 8;
            uint32_t ah[2][4], al[2][4];
#pragma unroll
            for (int ma = 0; ma < 2; ma++) {
                const int rb = (wm * 32 + ma * 16 + gid) * PAD + k0 + tig;
                ah[ma][0] = __float_as_uint(sAhi[rb]);
                ah[ma][1] = __float_as_uint(sAhi[rb + 8 * PAD]);
                ah[ma][2] = __float_as_uint(sAhi[rb + 4]);
                ah[ma][3] = __float_as_uint(sAhi[rb + 8 * PAD + 4]);
                al[ma][0] = __float_as_uint(sAlo[rb]);
                al[ma][1] = __float_as_uint(sAlo[rb + 8 * PAD]);
                al[ma][2] = __float_as_uint(sAlo[rb + 4]);
                al[ma][3] = __float_as_uint(sAlo[rb + 8 * PAD + 4]);
            }
            uint32_t bh[4][2], bl[4][2];
#pragma unroll
            for (int na = 0; na < 4; na++) {
                const int nb = (wn * 32 + na * 8 + gid) * PAD + k0 + tig;
                bh[na][0] = __float_as_uint(sBhi[nb]);
                bh[na][1] = __float_as_uint(sBhi[nb + 4]);
                bl[na][0] = __float_as_uint(sBlo[nb]);
                bl[na][1] = __float_as_uint(sBlo[nb + 4]);
            }
#pragma unroll
            for (int ma = 0; ma < 2; ma++)
#pragma unroll
                for (int na = 0; na < 4; na++) {
                    mma8(acc[ma][na], ah[ma], bh[na]);
                    mma8(acc[ma][na], ah[ma], bl[na]);
                    mma8(acc[ma][na], al[ma], bh[na]);
                }
        }
        __syncthreads();

        if (c == 7) {
#pragma unroll
            for (int ma = 0; ma < 2; ma++)
#pragma unroll
                for (int hl = 0; hl < 2; hl++) {
                    const int bi = ma * 2 + hl;
#pragma unroll
                    for (int na = 0; na < 4; na++) {
                        const int kk = nt * N_TILE + wn * 32 + na * 8 + tig * 2;
                        float c0 = s_cn[kk], c1 = s_cn[kk + 1];
                        float s0 = acc[ma][na][hl * 2 + 0];
                        float s1 = acc[ma][na][hl * 2 + 1];
                        float d0 = __fsub_rn(__fadd_rn(rn[bi], c0),
                                             __fmul_rn(2.0f, s0));
                        float d1 = __fsub_rn(__fadd_rn(rn[bi], c1),
                                             __fmul_rn(2.0f, s1));
                        if (d0 < best[bi]) { sec[bi] = best[bi]; best[bi] = d0; bestk[bi] = kk; }
                        else if (d0 < sec[bi]) sec[bi] = d0;
                        if (d1 < best[bi]) { sec[bi] = best[bi]; best[bi] = d1; bestk[bi] = kk + 1; }
                        else if (d1 < sec[bi]) sec[bi] = d1;
                    }
                }
        }
    }

    // --- cross-thread top-2 argmin reduce ---
    float* sb = (float*)(smem + OFF_SB);
    float* ssm = (float*)(smem + OFF_SS);
    int*   sk = (int*)(smem + OFF_SK);
#pragma unroll
    for (int bi = 0; bi < 4; bi++) {
        float b = best[bi], s2 = sec[bi];
        int bk = bestk[bi];
#pragma unroll
        for (int m = 1; m <= 2; m <<= 1) {
            float ob = __shfl_xor_sync(0xffffffff, b, m);
            float os = __shfl_xor_sync(0xffffffff, s2, m);
            int obk = __shfl_xor_sync(0xffffffff, bk, m);
            float ns = fminf(fmaxf(b, ob), fminf(s2, os));
            if (ob < b || (ob == b && obk < bk)) { b = ob; bk = obk; }
            s2 = ns;
        }
        if (tig == 0) {
            int row = wm * 32 + (bi >> 1) * 16 + (bi & 1) * 8 + gid;
            sb[row * 4 + wn] = b;
            ssm[row * 4 + wn] = s2;
            sk[row * 4 + wn] = bk;
        }
    }
    __syncthreads();
    if (tid < 128) {
        float b = sb[tid * 4], s2 = ssm[tid * 4];
        int bk = sk[tid * 4];
#pragma unroll
        for (int w = 1; w < 4; w++) {
            float v = sb[tid * 4 + w];
            float vs = ssm[tid * 4 + w];
            int vk = sk[tid * 4 + w];
            float ns = fminf(fmaxf(b, v), fminf(s2, vs));
            if (v < b || (v == b && vk < bk)) { b = v; bk = vk; }
            s2 = ns;
        }
        int row = row0 + tid;
        g_rowk[row] = bk;
        if (s2 - b < GAP_THRESH) {
            int i = atomicAdd(&g_nflag, 1);
            g_flagrows[i] = row;
        }
    }
}

// ---------------------------------------------------------------------------
// Rescue: recompute flagged rows with exact R2 semantics (serial in-order
// fp32 FMA, dist = fl(fl(r+c) - 2*sim), first-index tie-break).
__global__ void rescue_kernel(const float* __restrict__ x) {
    __shared__ float srow[8][D_DIM];
    const int lane = threadIdx.x & 31;
    const int wl = threadIdx.x >> 5;
    const int wglobal = (blockIdx.x * blockDim.x + threadIdx.x) >> 5;
    const int nw = (gridDim.x * blockDim.x) >> 5;
    const int nf = g_nflag;

    for (int i = wglobal; i < nf; i += nw) {
        const int row = g_flagrows[i];
        ((float4*)srow[wl])[lane] = ((const float4*)(x + (size_t)row * D_DIM))[lane];
        ((float4*)srow[wl])[lane + 32] = ((const float4*)(x + (size_t)row * D_DIM))[lane + 32];
        __syncwarp();
        const float r = g_rnorm[row];
        float best = 3.4e38f;
        int bk = 0;
        for (int j = 0; j < 32; j++) {
            const int k = lane + j * 32;
            const float* dp = g_dictT + (size_t)k * D_DIM;
            float sim = 0.f;
#pragma unroll 8
            for (int d = 0; d < D_DIM; d++)
                sim = __fmaf_rn(srow[wl][d], dp[d], sim);
            float dist = __fsub_rn(__fadd_rn(r, g_cnorm[k]),
                                   __fmul_rn(2.0f, sim));
            if (dist < best) { best = dist; bk = k; }
        }
#pragma unroll
        for (int m = 1; m < 32; m <<= 1) {
            float ob = __shfl_xor_sync(0xffffffff, best, m);
            int obk = __shfl_xor_sync(0xffffffff, bk, m);
            if (ob < best || (ob == best && obk < bk)) { best = ob; bk = obk; }
        }
        if (lane == 0) g_rowk[row] = bk;
        __syncwarp();
    }
}

// ---------------------------------------------------------------------------
// Output: gather + STE write + loss.
__global__ __launch_bounds__(256) void output_kernel(const float* __restrict__ x,
                                                     float* __restrict__ out) {
    const int tid = threadIdx.x;
    double ls = 0.0;
    for (int r = blockIdx.x; r < N_ROWS; r += gridDim.x) {
        int k = g_rowk[r];
        float qv = 0.5f * g_dictT[(size_t)k * D_DIM + tid];
        float xv = x[(size_t)r * D_DIM + tid];
        out[(size_t)r * D_DIM + tid] = __fadd_rn(xv, __fsub_rn(qv, xv));
        float df = xv - qv;
        ls += (double)df * (double)df;
    }
    __shared__ double sred[256];
    sred[tid] = ls;
    __syncthreads();
    for (int s = 128; s > 0; s >>= 1) {
        if (tid < s) sred[tid] += sred[tid + s];
        __syncthreads();
    }
    if (tid == 0) atomicAdd(&g_sum, sred[0]);
}

// ---------------------------------------------------------------------------
__global__ void finalize_kernel(float* out, long long total, int loss_idx) {
    out[loss_idx] = (float)(1.25 * g_sum / (double)total);
}

// ---------------------------------------------------------------------------
extern "C" void kernel_launch(void* const* d_in, const int* in_sizes, int n_in,
                              void* d_out, int out_size) {
    const float* x    = (const float*)d_in[0];
    const float* dict = (const float*)d_in[1];
    float* out = (float*)d_out;

    int Nel = in_sizes[0];                   // 16777216
    int n_mtiles = Nel / D_DIM / M_TILE;     // 512

    cudaFuncSetAttribute(vq_tc, cudaFuncAttributeMaxDynamicSharedMemorySize,
                         SMEM_TOTAL);

    split_dict_kernel<<<(K_CODES * 32 + 255) / 256, 256>>>(dict);
    split_x_kernel<<<(N_ROWS * 32 + 255) / 256, 256>>>(x);
    vq_tc<<<n_mtiles, 512, SMEM_TOTAL>>>();
    rescue_kernel<<<256, 256>>>(x);
    output_kernel<<<1024, 256>>>(x, out);
    if (out_size > Nel) {
        finalize_kernel<<<1, 1>>>(out, (long long)Nel, out_size - 1);
    }
}

// round 9
// speedup vs baseline: 1.8779x; 1.8779x over previous
#include <cuda_runtime.h>
#include <cstdint>

// VQBlock: x [65536, 256] fp32, dict [256, 1024] fp32.
// out[0..N*D) = q_st = x + (0.5*dict[:,argmin] - x), out[N*D] = 1.25*mean((x-q)^2)
//
// Round 9 (= R8 resubmit after infra failure): FFMA2 GEMM (bit-identical
// arithmetic to R3 which scored rel_err 0.0) with: A-tile resident in smem
// (loaded once, broadcast scalar LDS frags), cp.async double-buffered B
// stages, software-pipelined fragment prefetch.

#define D_DIM 256
#define K_DIM 1024
#define N_ROWS 65536
#define TM 128
#define TN 128
#define KD 16
#define NSTAGES 128   // 8 chunks x 16 depth-stages

// dynamic smem offsets (bytes)
#define OFF_A     0                       // 128*256*4 = 131072
#define OFF_B     131072                  // 2*16*128*4 = 16384
#define OFF_RS    147456                  // 128*16*4 = 8192
#define OFF_RI    155648                  // 8192
#define OFF_SROWK 163840                  // 512
#define OFF_SRED  164352                  // 2048
#define SMEM_TOTAL 166400

__device__ float  g_cnorm[K_DIM];          // ||dict[:,k]||^2 (fp32 from double)
__device__ float  g_rnorm[N_ROWS];         // ||x_row||^2 (fp32 from double)
__device__ float  g_dictT[K_DIM * D_DIM];  // [code][d]
__device__ double g_sum;

// ---------------------------------------------------------------------------
__device__ __forceinline__ uint32_t smem_u32(const void* p) {
    uint32_t a;
    asm("{ .reg .u64 t; cvta.to.shared.u64 t, %1; cvt.u32.u64 %0, t; }"
        : "=r"(a) : "l"(p));
    return a;
}
__device__ __forceinline__ void cp16(uint32_t dst, const void* src) {
    asm volatile("cp.async.cg.shared.global [%0], [%1], 16;"
                 :: "r"(dst), "l"(src) : "memory");
}
__device__ __forceinline__ unsigned long long pack_dup(float v) {
    unsigned int b = __float_as_uint(v);
    unsigned long long r;
    asm("mov.b64 %0, {%1, %2};" : "=l"(r) : "r"(b), "r"(b));
    return r;
}
__device__ __forceinline__ void unpack2(unsigned long long p, float& lo, float& hi) {
    unsigned int a, b;
    asm("mov.b64 {%0, %1}, %2;" : "=r"(a), "=r"(b) : "l"(p));
    lo = __uint_as_float(a);
    hi = __uint_as_float(b);
}
__device__ __forceinline__ void ffma2(unsigned long long& acc,
                                      unsigned long long a,
                                      unsigned long long b) {
    asm("fma.rn.f32x2 %0, %1, %2, %0;" : "+l"(acc) : "l"(a), "l"(b));
}

// ---------------------------------------------------------------------------
// prep: col norms (warp per code) + transposed dict
__global__ void colnorm_kernel(const float* __restrict__ dict) {
    int gt = blockIdx.x * blockDim.x + threadIdx.x;
    if (gt == 0) g_sum = 0.0;
    int warp = gt >> 5;
    int lane = threadIdx.x & 31;
    if (warp >= K_DIM) return;
    double s = 0.0;
    for (int d = lane; d < D_DIM; d += 32) {
        float v = dict[d * K_DIM + warp];
        s += (double)v * v;
        g_dictT[(size_t)warp * D_DIM + d] = v;
    }
#pragma unroll
    for (int o = 16; o > 0; o >>= 1) s += __shfl_xor_sync(0xffffffff, s, o);
    if (lane == 0) g_cnorm[warp] = (float)s;
}

__global__ void rownorm_kernel(const float* __restrict__ x) {
    int warp = (blockIdx.x * blockDim.x + threadIdx.x) >> 5;
    int lane = threadIdx.x & 31;
    if (warp >= N_ROWS) return;
    const float4* p = (const float4*)(x + (size_t)warp * D_DIM);
    float4 a = p[lane];
    float4 b = p[lane + 32];
    double s = (double)a.x * a.x + (double)a.y * a.y
             + (double)a.z * a.z + (double)a.w * a.w
             + (double)b.x * b.x + (double)b.y * b.y
             + (double)b.z * b.z + (double)b.w * b.w;
#pragma unroll
    for (int o = 16; o > 0; o >>= 1) s += __shfl_xor_sync(0xffffffff, s, o);
    if (lane == 0) g_rnorm[warp] = (float)s;
}

// ---------------------------------------------------------------------------
// 256 threads, one 128-row tile per block, all 1024 codes in 8 chunks of 128.
// 8x8 microtile per thread (as 8x4 FFMA2 pairs).
__global__ __launch_bounds__(256) void vq_main(const float* __restrict__ x,
                                               const float* __restrict__ dict,
                                               float* __restrict__ out) {
    extern __shared__ char smem[];
    const uint32_t smu = smem_u32(smem);
    float* As = (float*)(smem + OFF_A);          // [128][256] row-major
    const int tid = threadIdx.x;
    const int tx = tid & 15;
    const int ty = tid >> 4;
    const int row0 = blockIdx.x * TM;

    // ---- A tile: 128 rows x 256 d, once, via cp.async (coalesced) ----
    {
        uint32_t abase = smu + OFF_A;
#pragma unroll
        for (int i = 0; i < 32; i++) {
            int q = i * 256 + tid;        // 8192 float4
            int r = q >> 6;               // row
            int d4 = q & 63;              // float4 within row
            cp16(abase + (uint32_t)(r * 1024 + d4 * 16),
                 x + (size_t)(row0 + r) * D_DIM + d4 * 4);
        }
        asm volatile("cp.async.commit_group;" ::: "memory");
    }

    // ---- B stage issue: 16 depths x 128 codes (8KB) ----
    auto issueB = [&](int g) {
        int chunk = (g >> 4) * TN;
        int d0 = (g & 15) * KD;
        uint32_t bbase = smu + OFF_B + (uint32_t)(g & 1) * 8192;
        int brow = tid >> 4;              // 0..15 depth
        int bc = (tid & 15) * 8;          // col (2x16B)
        const float* src = dict + (size_t)(d0 + brow) * K_DIM + chunk + bc;
        uint32_t dst = bbase + (uint32_t)(brow * 512 + bc * 4);
        cp16(dst, src);
        cp16(dst + 16, src + 4);
        asm volatile("cp.async.commit_group;" ::: "memory");
    };

    float best[8];
    int   bestk[8];
    float r8[8];
#pragma unroll
    for (int i = 0; i < 8; i++) {
        best[i] = 3.4e38f;
        bestk[i] = 0;
        r8[i] = g_rnorm[row0 + ty * 8 + i];
    }

    issueB(0);

    unsigned long long acc2[8][4];

    for (int g = 0; g < NSTAGES; g++) {
        if (g + 1 < NSTAGES) {
            issueB(g + 1);
            asm volatile("cp.async.wait_group 1;" ::: "memory");
        } else {
            asm volatile("cp.async.wait_group 0;" ::: "memory");
        }
        __syncthreads();

        if ((g & 15) == 0) {
#pragma unroll
            for (int i = 0; i < 8; i++)
#pragma unroll
                for (int j = 0; j < 4; j++) acc2[i][j] = 0ull;
        }

        const int d0 = (g & 15) * KD;
        const float* Bs = (const float*)(smem + OFF_B + (g & 1) * 8192);
        const float* arow = As + ty * 8 * 256 + d0;   // + i*256 + dd

        // software-pipelined fragment loads over dd
        float af[2][8];
        unsigned long long bf[2][4];
#pragma unroll
        for (int i = 0; i < 8; i++) af[0][i] = arow[i * 256];
        *(ulonglong2*)&bf[0][0] = *(const ulonglong2*)&Bs[tx * 8];
        *(ulonglong2*)&bf[0][2] = *(const ulonglong2*)&Bs[tx * 8 + 4];

#pragma unroll
        for (int dd = 0; dd < KD; dd++) {
            const int cur = dd & 1, nxt = cur ^ 1;
            if (dd + 1 < KD) {
#pragma unroll
                for (int i = 0; i < 8; i++) af[nxt][i] = arow[i * 256 + dd + 1];
                *(ulonglong2*)&bf[nxt][0] =
                    *(const ulonglong2*)&Bs[(dd + 1) * 128 + tx * 8];
                *(ulonglong2*)&bf[nxt][2] =
                    *(const ulonglong2*)&Bs[(dd + 1) * 128 + tx * 8 + 4];
            }
#pragma unroll
            for (int i = 0; i < 8; i++) {
                unsigned long long a2 = pack_dup(af[cur][i]);
#pragma unroll
                for (int j = 0; j < 4; j++)
                    ffma2(acc2[i][j], a2, bf[cur][j]);
            }
        }
        __syncthreads();   // frags consumed before next stage overwrites buf

        if ((g & 15) == 15) {
            // chunk epilogue: dist = fl(fl(r + c) - 2*sim), first-index argmin
            const int chunk = (g >> 4) * TN;
#pragma unroll
            for (int j = 0; j < 4; j++) {
                int k0 = chunk + tx * 8 + 2 * j;
                float c0 = g_cnorm[k0];
                float c1 = g_cnorm[k0 + 1];
#pragma unroll
                for (int i = 0; i < 8; i++) {
                    float s0, s1;
                    unpack2(acc2[i][j], s0, s1);
                    float d0v = __fsub_rn(__fadd_rn(r8[i], c0),
                                          __fmul_rn(2.0f, s0));
                    float d1v = __fsub_rn(__fadd_rn(r8[i], c1),
                                          __fmul_rn(2.0f, s1));
                    if (d0v < best[i]) { best[i] = d0v; bestk[i] = k0; }
                    if (d1v < best[i]) { best[i] = d1v; bestk[i] = k0 + 1; }
                }
            }
        }
    }

    // ---- cross-thread argmin reduce ----
    float* rs = (float*)(smem + OFF_RS);   // [128][16]
    int*   ri = (int*)(smem + OFF_RI);
    int*   srow_k = (int*)(smem + OFF_SROWK);
    __syncthreads();
#pragma unroll
    for (int i = 0; i < 8; i++) {
        rs[(ty * 8 + i) * 16 + tx] = best[i];
        ri[(ty * 8 + i) * 16 + tx] = bestk[i];
    }
    __syncthreads();
    if (tid < TM) {
        float b = rs[tid * 16];
        int  bk = ri[tid * 16];
#pragma unroll
        for (int t = 1; t < 16; t++) {
            float v = rs[tid * 16 + t];
            int  vk = ri[tid * 16 + t];
            if (v < b || (v == b && vk < bk)) { b = v; bk = vk; }
        }
        srow_k[tid] = bk;
    }
    __syncthreads();

    // ---- output q_st + loss ----
    double lsum = 0.0;
    for (int e = tid; e < TM * D_DIM; e += 256) {
        int r = e >> 8;
        int d = e & 255;
        int k = srow_k[r];
        float qv = 0.5f * g_dictT[(size_t)k * D_DIM + d];
        float xv = x[(size_t)(row0 + r) * D_DIM + d];
        out[(size_t)(row0 + r) * D_DIM + d] = __fadd_rn(xv, __fsub_rn(qv, xv));
        float df = xv - qv;
        lsum += (double)df * (double)df;
    }
    double* sred = (double*)(smem + OFF_SRED);
    sred[tid] = lsum;
    __syncthreads();
    for (int s = 128; s > 0; s >>= 1) {
        if (tid < s) sred[tid] += sred[tid + s];
        __syncthreads();
    }
    if (tid == 0) atomicAdd(&g_sum, sred[0]);
}

// ---------------------------------------------------------------------------
__global__ void finalize_kernel(float* out, long long total, int loss_idx) {
    out[loss_idx] = (float)(1.25 * g_sum / (double)total);
}

// ---------------------------------------------------------------------------
extern "C" void kernel_launch(void* const* d_in, const int* in_sizes, int n_in,
                              void* d_out, int out_size) {
    const float* x    = (const float*)d_in[0];
    const float* dict = (const float*)d_in[1];
    float* out = (float*)d_out;

    int Nel = in_sizes[0];     // 16777216
    int N   = Nel / D_DIM;     // 65536

    cudaFuncSetAttribute(vq_main, cudaFuncAttributeMaxDynamicSharedMemorySize,
                         SMEM_TOTAL);

    colnorm_kernel<<<(K_DIM * 32 + 255) / 256, 256>>>(dict);
    rownorm_kernel<<<(N * 32 + 255) / 256, 256>>>(x);
    vq_main<<<N / TM, 256, SMEM_TOTAL>>>(x, dict, out);
    if (out_size > Nel) {
        finalize_kernel<<<1, 1>>>(out, (long long)Nel, out_size - 1);
    }
}